// round 15
// baseline (speedup 1.0000x reference)
#include <cuda_runtime.h>
#include <math.h>

#define NT 4
#define PT 8192
#define NH 32
#define NU 128
#define NBLK (PT / 4)   // k1b blocks per type

// ---------------- scratch (device globals; no allocations) ----------------
__device__ float g_KT[NT * NU * NU];
__device__ float g_QK[NT * NU * NU];           // q_w @ k_w^T
__device__ float g_VF[NT * NU * NU];           // v_w @ fc_w
__device__ float g_QKX[(size_t)NT * PT * NU];  // x @ QK
__device__ float g_RAW[(size_t)NT * PT * NH];
__device__ float g_M[NT * NH];
__device__ float g_S[NT * NH];
__device__ int   g_ctr[NT];                    // k1b completion tickets

// ---------------- zero tickets (runs first every replay) ----------------
__global__ void kreset() {
    if (threadIdx.x < NT) g_ctr[threadIdx.x] = 0;
}

// ---------------- prep ----------------
__global__ void __launch_bounds__(256) ktrans(const float* __restrict__ kw) {
    __shared__ float tile[32][33];
    int t = blockIdx.z;
    int bx = blockIdx.x * 32, by = blockIdx.y * 32;
    const float* src = kw + (size_t)t * NU * NU;
    float* dst = g_KT + (size_t)t * NU * NU;
    int tx = threadIdx.x, ty = threadIdx.y;
#pragma unroll
    for (int i = 0; i < 32; i += 8)
        tile[ty + i][tx] = src[(by + ty + i) * NU + bx + tx];
    __syncthreads();
#pragma unroll
    for (int i = 0; i < 32; i += 8)
        dst[(bx + ty + i) * NU + by + tx] = tile[tx][ty + i];
}

__global__ void __launch_bounds__(128) kqk(const float* __restrict__ qw) {
    int t = blockIdx.y, e = blockIdx.x, u = threadIdx.x;
    const float* q = qw + ((size_t)t * NU + e) * NU;
    const float* kt = g_KT + (size_t)t * NU * NU;
    float acc = 0.f;
#pragma unroll 8
    for (int v = 0; v < NU; ++v)
        acc = fmaf(q[v], kt[v * NU + u], acc);
    g_QK[((size_t)t * NU + e) * NU + u] = acc;
}

__global__ void __launch_bounds__(128) kvf(const float* __restrict__ vw,
                                           const float* __restrict__ fw) {
    int t = blockIdx.y, w = blockIdx.x, j = threadIdx.x;
    const float* vr = vw + ((size_t)t * NU + w) * NU;
    const float* f = fw + (size_t)t * NU * NU;
    float acc = 0.f;
#pragma unroll 8
    for (int u = 0; u < NU; ++u)
        acc = fmaf(vr[u], f[u * NU + j], acc);
    g_VF[((size_t)t * NU + w) * NU + j] = acc;
}

// ============ split-N gathered GEMM: QKX[t][n][64*half..] = X[eidx] @ QK[:, half] ============
__global__ void __launch_bounds__(256) kgemmH(const float* __restrict__ state,
                                              const int* __restrict__ eidx,
                                              int t, float* __restrict__ dst) {
    extern __shared__ float smem[];
    float* sX = smem;                        // [64][128] = 32KB
    float4* sW4 = (float4*)(smem + 64 * NU); // [128][16] float4 = 32KB
    int n0 = blockIdx.x * 64;
    int half = blockIdx.y;

    const float4* w4 = (const float4*)(g_QK + (size_t)t * NU * NU);
#pragma unroll
    for (int i = threadIdx.x; i < 2048; i += 256)
        sW4[i] = w4[(i >> 4) * 32 + half * 16 + (i & 15)];

    float4* sX4 = (float4*)sX;
#pragma unroll
    for (int i = threadIdx.x; i < 2048; i += 256) {
        int r = i >> 5, c = i & 31;
        int idx = eidx[t * PT + n0 + r];
        sX4[i] = __ldg((const float4*)(state + (size_t)idx * NU) + c);
    }
    __syncthreads();

    int tx = threadIdx.x & 15;
    int ty = threadIdx.x >> 4;
    float4 acc[4];
#pragma unroll
    for (int i = 0; i < 4; ++i) acc[i] = make_float4(0.f, 0.f, 0.f, 0.f);
#pragma unroll 4
    for (int v = 0; v < NU; ++v) {
        float4 b = sW4[v * 16 + tx];
#pragma unroll
        for (int i = 0; i < 4; ++i) {
            float a = sX[(ty * 4 + i) * NU + v];
            acc[i].x = fmaf(a, b.x, acc[i].x);
            acc[i].y = fmaf(a, b.y, acc[i].y);
            acc[i].z = fmaf(a, b.z, acc[i].z);
            acc[i].w = fmaf(a, b.w, acc[i].w);
        }
    }
#pragma unroll
    for (int i = 0; i < 4; ++i)
        ((float4*)(dst + ((size_t)t * PT + n0 + ty * 4 + i) * NU))[half * 16 + tx] = acc[i];
}

// ============ k1bf(t): raw = hist . qkx, FUSED softmax stats (last-32-blocks) ============
__global__ void __launch_bounds__(128) k1bf(const float* __restrict__ hist,
                                            const int* __restrict__ eidx, int t) {
    int lane = threadIdx.x & 31;
    int warp = threadIdx.x >> 5;
    int n = blockIdx.x * 4 + warp;
    int idx = eidx[t * PT + n];
    int g = lane >> 3;
    int c = lane & 7;

    const float4* qkrow = (const float4*)(g_QKX + ((size_t)t * PT + n) * NU);
    float4 qk[4];
#pragma unroll
    for (int j = 0; j < 4; ++j) qk[j] = __ldg(qkrow + j * 8 + c);

    const float* hb = hist + (size_t)idx * NH * NU;
    float* rawdst = g_RAW + ((size_t)t * PT + n) * NH;
#pragma unroll
    for (int i = 0; i < 8; ++i) {
        const float4* rowp = (const float4*)(hb + (4 * i + g) * NU);
        float4 v0 = __ldcs(rowp + 0 * 8 + c);
        float4 v1 = __ldcs(rowp + 1 * 8 + c);
        float4 v2 = __ldcs(rowp + 2 * 8 + c);
        float4 v3 = __ldcs(rowp + 3 * 8 + c);
        float p = 0.f;
        p = fmaf(v0.x, qk[0].x, p); p = fmaf(v0.y, qk[0].y, p);
        p = fmaf(v0.z, qk[0].z, p); p = fmaf(v0.w, qk[0].w, p);
        p = fmaf(v1.x, qk[1].x, p); p = fmaf(v1.y, qk[1].y, p);
        p = fmaf(v1.z, qk[1].z, p); p = fmaf(v1.w, qk[1].w, p);
        p = fmaf(v2.x, qk[2].x, p); p = fmaf(v2.y, qk[2].y, p);
        p = fmaf(v2.z, qk[2].z, p); p = fmaf(v2.w, qk[2].w, p);
        p = fmaf(v3.x, qk[3].x, p); p = fmaf(v3.y, qk[3].y, p);
        p = fmaf(v3.z, qk[3].z, p); p = fmaf(v3.w, qk[3].w, p);
        p += __shfl_xor_sync(0xffffffffu, p, 4);
        p += __shfl_xor_sync(0xffffffffu, p, 2);
        p += __shfl_xor_sync(0xffffffffu, p, 1);
        if (c == 0) rawdst[4 * i + g] = p;
    }

    // ---- ticket: last 32 blocks compute softmax stats, one h each ----
    __shared__ int sticket;
    __threadfence();                       // raws visible before ticket
    __syncthreads();
    if (threadIdx.x == 0)
        sticket = atomicAdd(&g_ctr[t], 1);
    __syncthreads();
    int ticket = sticket;
    if (ticket < NBLK - NH) return;

    // wait until all blocks of this type have finished their raw stores
    if (threadIdx.x == 0)
        while (*(volatile int*)&g_ctr[t] < NBLK) { }
    __syncthreads();
    __threadfence();

    int h = ticket - (NBLK - NH);
    const float* base = g_RAW + (size_t)t * PT * NH + h;
    __shared__ float rm[128], rs[128];
    int tid = threadIdx.x;
    float m = -3.402823466e+38f, s = 0.f;
    for (int e = tid; e < PT; e += 128) {
        float x = base[(size_t)e * NH];
        if (x > m) { s = s * expf(m - x) + 1.f; m = x; }
        else s += expf(x - m);
    }
    rm[tid] = m; rs[tid] = s;
    __syncthreads();
#pragma unroll
    for (int st = 64; st; st >>= 1) {
        if (tid < st) {
            float m2 = rm[tid + st], s2 = rs[tid + st];
            float M = fmaxf(rm[tid], m2);
            rs[tid] = rs[tid] * expf(rm[tid] - M) + s2 * expf(m2 - M);
            rm[tid] = M;
        }
        __syncthreads();
    }
    if (tid == 0) { g_M[t * NH + h] = rm[0]; g_S[t * NH + h] = rs[0]; }
}

// ============ kout3(t): sparse-hbar + relu(hbar @ VF) + X @ qw ============
// Sparse-hbar is bit-exact: fp32 softmax weights underflow to exactly 0.0 away from the
// per-(t,h) argmax; the fp32 reference underflows identically, and fmaf(0, x, a) == a.
__global__ void __launch_bounds__(256) kout3(const float* __restrict__ state,
                                             const float* __restrict__ hist,
                                             const int* __restrict__ eidx,
                                             const float* __restrict__ qw,
                                             float* __restrict__ out, int t) {
    extern __shared__ float smem[];
    float* sX = smem;                        // [64][128]
    float4* sW4 = (float4*)(smem + 64 * NU); // [128][16] float4
    int n0 = blockIdx.x * 64;
    int half = blockIdx.y;
    int lane = threadIdx.x & 31;
    int warp = threadIdx.x >> 5;
    int tx = threadIdx.x & 15;
    int ty = threadIdx.x >> 4;

    {
        const float4* w4 = (const float4*)(g_VF + (size_t)t * NU * NU);
#pragma unroll
        for (int i = threadIdx.x; i < 2048; i += 256)
            sW4[i] = w4[(i >> 4) * 32 + half * 16 + (i & 15)];
    }

    {
        float Mv = g_M[t * NH + lane];
        float Sv = g_S[t * NH + lane];
#pragma unroll
        for (int j = 0; j < 8; ++j) {
            int r = warp * 8 + j;
            int n = n0 + r;
            int idx = eidx[t * PT + n];
            float raw = g_RAW[((size_t)t * PT + n) * NH + lane];
            float wv = expf(raw - Mv) / Sv;
            unsigned mask = __ballot_sync(0xffffffffu, wv != 0.0f);
            float4 hbv = make_float4(0.f, 0.f, 0.f, 0.f);
            const float4* h4 = (const float4*)(hist + (size_t)idx * NH * NU);
            while (mask) {
                int h = __ffs(mask) - 1;
                mask &= mask - 1;
                float wh = __shfl_sync(0xffffffffu, wv, h);
                float4 r4 = __ldg(h4 + h * 32 + lane);
                hbv.x = fmaf(wh, r4.x, hbv.x); hbv.y = fmaf(wh, r4.y, hbv.y);
                hbv.z = fmaf(wh, r4.z, hbv.z); hbv.w = fmaf(wh, r4.w, hbv.w);
            }
            ((float4*)(sX + r * NU))[lane] = hbv;
        }
    }
    __syncthreads();

    float4 a1[4];
#pragma unroll
    for (int i = 0; i < 4; ++i) a1[i] = make_float4(0.f, 0.f, 0.f, 0.f);
#pragma unroll 4
    for (int v = 0; v < NU; ++v) {
        float4 b = sW4[v * 16 + tx];
#pragma unroll
        for (int i = 0; i < 4; ++i) {
            float a = sX[(ty * 4 + i) * NU + v];
            a1[i].x = fmaf(a, b.x, a1[i].x);
            a1[i].y = fmaf(a, b.y, a1[i].y);
            a1[i].z = fmaf(a, b.z, a1[i].z);
            a1[i].w = fmaf(a, b.w, a1[i].w);
        }
    }
    __syncthreads();

    {
        const float4* w4 = (const float4*)(qw + (size_t)t * NU * NU);
#pragma unroll
        for (int i = threadIdx.x; i < 2048; i += 256)
            sW4[i] = w4[(i >> 4) * 32 + half * 16 + (i & 15)];
        float4* sX4 = (float4*)sX;
#pragma unroll
        for (int i = threadIdx.x; i < 2048; i += 256) {
            int r = i >> 5, c = i & 31;
            int idx = eidx[t * PT + n0 + r];
            sX4[i] = __ldg((const float4*)(state + (size_t)idx * NU) + c);
        }
    }
    __syncthreads();

    float4 a2[4];
#pragma unroll
    for (int i = 0; i < 4; ++i) a2[i] = make_float4(0.f, 0.f, 0.f, 0.f);
#pragma unroll 4
    for (int v = 0; v < NU; ++v) {
        float4 b = sW4[v * 16 + tx];
#pragma unroll
        for (int i = 0; i < 4; ++i) {
            float a = sX[(ty * 4 + i) * NU + v];
            a2[i].x = fmaf(a, b.x, a2[i].x);
            a2[i].y = fmaf(a, b.y, a2[i].y);
            a2[i].z = fmaf(a, b.z, a2[i].z);
            a2[i].w = fmaf(a, b.w, a2[i].w);
        }
    }

#pragma unroll
    for (int i = 0; i < 4; ++i) {
        size_t row = (size_t)t * PT + n0 + ty * 4 + i;
        float4 r;
        r.x = fmaxf(a1[i].x, 0.f) + a2[i].x;
        r.y = fmaxf(a1[i].y, 0.f) + a2[i].y;
        r.z = fmaxf(a1[i].z, 0.f) + a2[i].z;
        r.w = fmaxf(a1[i].w, 0.f) + a2[i].w;
        ((float4*)(out + row * NU))[half * 16 + tx] = r;
    }
}

// ---------------- launch ----------------
extern "C" void kernel_launch(void* const* d_in, const int* in_sizes, int n_in,
                              void* d_out, int out_size) {
    const float* state = (const float*)d_in[0];
    const float* hist  = (const float*)d_in[1];
    const int*   eidx  = (const int*)d_in[2];
    const float* qw    = (const float*)d_in[3];
    const float* kw    = (const float*)d_in[4];
    const float* vw    = (const float*)d_in[5];
    const float* fw    = (const float*)d_in[6];
    float* out = (float*)d_out;

    const int GSMEM = 64 * 1024;

    static bool init_done = false;
    static cudaStream_t s1, s2;
    static cudaEvent_t eP, gE[NT], hE[NT], e1, fE;
    static float* p_QKX;
    if (!init_done) {
        cudaFuncSetAttribute(kgemmH, cudaFuncAttributeMaxDynamicSharedMemorySize, GSMEM);
        cudaFuncSetAttribute(kout3, cudaFuncAttributeMaxDynamicSharedMemorySize, GSMEM);
        int lo, hi;
        cudaDeviceGetStreamPriorityRange(&lo, &hi);
        cudaStreamCreateWithPriority(&s1, cudaStreamNonBlocking, hi);
        cudaStreamCreateWithPriority(&s2, cudaStreamNonBlocking, lo);
        cudaEventCreateWithFlags(&eP, cudaEventDisableTiming);
        for (int t = 0; t < NT; ++t) {
            cudaEventCreateWithFlags(&gE[t], cudaEventDisableTiming);
            cudaEventCreateWithFlags(&hE[t], cudaEventDisableTiming);
        }
        cudaEventCreateWithFlags(&e1, cudaEventDisableTiming);
        cudaEventCreateWithFlags(&fE, cudaEventDisableTiming);
        cudaGetSymbolAddress((void**)&p_QKX, g_QKX);
        init_done = true;
    }

    // ---- s0: reset tickets, prep, per-type QKX GEMMs ----
    kreset<<<1, 32>>>();
    ktrans<<<dim3(4, 4, NT), dim3(32, 8)>>>(kw);
    kqk<<<dim3(NU, NT), NU>>>(qw);
    cudaEventRecord(eP, 0);
    for (int t = 0; t < NT; ++t) {
        kgemmH<<<dim3(PT / 64, 2), 256, GSMEM>>>(state, eidx, t, p_QKX);
        cudaEventRecord(gE[t], 0);
    }

    // ---- s1 (high prio): per-type fused k1b+stats ----
    for (int t = 0; t < NT; ++t) {
        cudaStreamWaitEvent(s1, gE[t], 0);
        k1bf<<<NBLK, 128, 0, s1>>>(hist, eidx, t);
        cudaEventRecord(hE[t], s1);
    }
    cudaEventRecord(e1, s1);

    // ---- s2 (low prio): kvf hidden; fully-fused epilogue per type ----
    cudaStreamWaitEvent(s2, eP, 0);
    kvf<<<dim3(NU, NT), NU, 0, s2>>>(vw, fw);
    for (int t = 0; t < NT; ++t) {
        cudaStreamWaitEvent(s2, hE[t], 0);
        kout3<<<dim3(PT / 64, 2), 256, GSMEM, s2>>>(state, hist, eidx, qw, out, t);
    }
    cudaEventRecord(fE, s2);

    // ---- join ----
    cudaStreamWaitEvent(0, e1, 0);
    cudaStreamWaitEvent(0, fE, 0);
}

// round 16
// speedup vs baseline: 1.2093x; 1.2093x over previous
#include <cuda_runtime.h>
#include <math.h>

#define NT 4
#define PT 8192
#define NH 32
#define NU 128

// ---------------- scratch (device globals; no allocations) ----------------
__device__ float g_KT[NT * NU * NU];
__device__ float g_QK[NT * NU * NU];           // q_w @ k_w^T
__device__ float g_VF[NT * NU * NU];           // v_w @ fc_w
__device__ float g_QKX[(size_t)NT * PT * NU];  // x @ QK
__device__ float g_RAW[(size_t)NT * PT * NH];
__device__ float g_M[NT * NH];
__device__ float g_S[NT * NH];

// ---------------- prep ----------------
__global__ void __launch_bounds__(256) ktrans(const float* __restrict__ kw) {
    __shared__ float tile[32][33];
    int t = blockIdx.z;
    int bx = blockIdx.x * 32, by = blockIdx.y * 32;
    const float* src = kw + (size_t)t * NU * NU;
    float* dst = g_KT + (size_t)t * NU * NU;
    int tx = threadIdx.x, ty = threadIdx.y;
#pragma unroll
    for (int i = 0; i < 32; i += 8)
        tile[ty + i][tx] = src[(by + ty + i) * NU + bx + tx];
    __syncthreads();
#pragma unroll
    for (int i = 0; i < 32; i += 8)
        dst[(bx + ty + i) * NU + by + tx] = tile[tx][ty + i];
}

__global__ void __launch_bounds__(128) kqk(const float* __restrict__ qw) {
    int t = blockIdx.y, e = blockIdx.x, u = threadIdx.x;
    const float* q = qw + ((size_t)t * NU + e) * NU;
    const float* kt = g_KT + (size_t)t * NU * NU;
    float acc = 0.f;
#pragma unroll 8
    for (int v = 0; v < NU; ++v)
        acc = fmaf(q[v], kt[v * NU + u], acc);
    g_QK[((size_t)t * NU + e) * NU + u] = acc;
}

__global__ void __launch_bounds__(128) kvf(const float* __restrict__ vw,
                                           const float* __restrict__ fw) {
    int t = blockIdx.y, w = blockIdx.x, j = threadIdx.x;
    const float* vr = vw + ((size_t)t * NU + w) * NU;
    const float* f = fw + (size_t)t * NU * NU;
    float acc = 0.f;
#pragma unroll 8
    for (int u = 0; u < NU; ++u)
        acc = fmaf(vr[u], f[u * NU + j], acc);
    g_VF[((size_t)t * NU + w) * NU + j] = acc;
}

// ============ split-N gathered GEMM: QKX[t][n][64*half..] = X[eidx] @ QK[:, half] ============
__global__ void __launch_bounds__(256) kgemmH(const float* __restrict__ state,
                                              const int* __restrict__ eidx,
                                              int t, float* __restrict__ dst) {
    extern __shared__ float smem[];
    float* sX = smem;                        // [64][128] = 32KB
    float4* sW4 = (float4*)(smem + 64 * NU); // [128][16] float4 = 32KB
    int n0 = blockIdx.x * 64;
    int half = blockIdx.y;

    const float4* w4 = (const float4*)(g_QK + (size_t)t * NU * NU);
#pragma unroll
    for (int i = threadIdx.x; i < 2048; i += 256)
        sW4[i] = w4[(i >> 4) * 32 + half * 16 + (i & 15)];

    float4* sX4 = (float4*)sX;
#pragma unroll
    for (int i = threadIdx.x; i < 2048; i += 256) {
        int r = i >> 5, c = i & 31;
        int idx = eidx[t * PT + n0 + r];
        sX4[i] = __ldg((const float4*)(state + (size_t)idx * NU) + c);
    }
    __syncthreads();

    int tx = threadIdx.x & 15;
    int ty = threadIdx.x >> 4;
    float4 acc[4];
#pragma unroll
    for (int i = 0; i < 4; ++i) acc[i] = make_float4(0.f, 0.f, 0.f, 0.f);
#pragma unroll 4
    for (int v = 0; v < NU; ++v) {
        float4 b = sW4[v * 16 + tx];
#pragma unroll
        for (int i = 0; i < 4; ++i) {
            float a = sX[(ty * 4 + i) * NU + v];
            acc[i].x = fmaf(a, b.x, acc[i].x);
            acc[i].y = fmaf(a, b.y, acc[i].y);
            acc[i].z = fmaf(a, b.z, acc[i].z);
            acc[i].w = fmaf(a, b.w, acc[i].w);
        }
    }
#pragma unroll
    for (int i = 0; i < 4; ++i)
        ((float4*)(dst + ((size_t)t * PT + n0 + ty * 4 + i) * NU))[half * 16 + tx] = acc[i];
}

// ============ k1b(t): raw = hist . qkx — quarter-warp rows, evict-first stream ============
__global__ void __launch_bounds__(128) k1b(const float* __restrict__ hist,
                                           const int* __restrict__ eidx, int t) {
    int lane = threadIdx.x & 31;
    int warp = threadIdx.x >> 5;
    int n = blockIdx.x * 4 + warp;
    int idx = eidx[t * PT + n];
    int g = lane >> 3;
    int c = lane & 7;

    const float4* qkrow = (const float4*)(g_QKX + ((size_t)t * PT + n) * NU);
    float4 qk[4];
#pragma unroll
    for (int j = 0; j < 4; ++j) qk[j] = __ldg(qkrow + j * 8 + c);

    const float* hb = hist + (size_t)idx * NH * NU;
    float* rawdst = g_RAW + ((size_t)t * PT + n) * NH;
#pragma unroll
    for (int i = 0; i < 8; ++i) {
        const float4* rowp = (const float4*)(hb + (4 * i + g) * NU);
        float4 v0 = __ldcs(rowp + 0 * 8 + c);
        float4 v1 = __ldcs(rowp + 1 * 8 + c);
        float4 v2 = __ldcs(rowp + 2 * 8 + c);
        float4 v3 = __ldcs(rowp + 3 * 8 + c);
        float p = 0.f;
        p = fmaf(v0.x, qk[0].x, p); p = fmaf(v0.y, qk[0].y, p);
        p = fmaf(v0.z, qk[0].z, p); p = fmaf(v0.w, qk[0].w, p);
        p = fmaf(v1.x, qk[1].x, p); p = fmaf(v1.y, qk[1].y, p);
        p = fmaf(v1.z, qk[1].z, p); p = fmaf(v1.w, qk[1].w, p);
        p = fmaf(v2.x, qk[2].x, p); p = fmaf(v2.y, qk[2].y, p);
        p = fmaf(v2.z, qk[2].z, p); p = fmaf(v2.w, qk[2].w, p);
        p = fmaf(v3.x, qk[3].x, p); p = fmaf(v3.y, qk[3].y, p);
        p = fmaf(v3.z, qk[3].z, p); p = fmaf(v3.w, qk[3].w, p);
        p += __shfl_xor_sync(0xffffffffu, p, 4);
        p += __shfl_xor_sync(0xffffffffu, p, 2);
        p += __shfl_xor_sync(0xffffffffu, p, 1);
        if (c == 0) rawdst[4 * i + g] = p;
    }
}

// ---------------- k2t(t): softmax stats for one type ----------------
__global__ void __launch_bounds__(256) k2t(int t) {
    int h = blockIdx.x;
    const float* base = g_RAW + (size_t)t * PT * NH + h;
    __shared__ float rm[256], rs[256];
    int tid = threadIdx.x;

    float m = -3.402823466e+38f, s = 0.f;
    for (int n = tid; n < PT; n += 256) {
        float x = base[(size_t)n * NH];
        if (x > m) { s = s * expf(m - x) + 1.f; m = x; }
        else s += expf(x - m);
    }
    rm[tid] = m; rs[tid] = s;
    __syncthreads();
#pragma unroll
    for (int st = 128; st; st >>= 1) {
        if (tid < st) {
            float m2 = rm[tid + st], s2 = rs[tid + st];
            float M = fmaxf(rm[tid], m2);
            rs[tid] = rs[tid] * expf(rm[tid] - M) + s2 * expf(m2 - M);
            rm[tid] = M;
        }
        __syncthreads();
    }
    if (tid == 0) { g_M[t * NH + h] = rm[0]; g_S[t * NH + h] = rs[0]; }
}

// ============ kout3(t): sparse-hbar + relu(hbar @ VF) + X @ qw ============
// Sparse-hbar is bit-exact: fp32 softmax weights underflow to exactly 0.0 away from the
// per-(t,h) argmax; the fp32 reference underflows identically, and fmaf(0, x, a) == a.
__global__ void __launch_bounds__(256) kout3(const float* __restrict__ state,
                                             const float* __restrict__ hist,
                                             const int* __restrict__ eidx,
                                             const float* __restrict__ qw,
                                             float* __restrict__ out, int t) {
    extern __shared__ float smem[];
    float* sX = smem;                        // [64][128]
    float4* sW4 = (float4*)(smem + 64 * NU); // [128][16] float4
    int n0 = blockIdx.x * 64;
    int half = blockIdx.y;
    int lane = threadIdx.x & 31;
    int warp = threadIdx.x >> 5;
    int tx = threadIdx.x & 15;
    int ty = threadIdx.x >> 4;

    {
        const float4* w4 = (const float4*)(g_VF + (size_t)t * NU * NU);
#pragma unroll
        for (int i = threadIdx.x; i < 2048; i += 256)
            sW4[i] = w4[(i >> 4) * 32 + half * 16 + (i & 15)];
    }

    {
        float Mv = g_M[t * NH + lane];
        float Sv = g_S[t * NH + lane];
#pragma unroll
        for (int j = 0; j < 8; ++j) {
            int r = warp * 8 + j;
            int n = n0 + r;
            int idx = eidx[t * PT + n];
            float raw = g_RAW[((size_t)t * PT + n) * NH + lane];
            float wv = expf(raw - Mv) / Sv;
            unsigned mask = __ballot_sync(0xffffffffu, wv != 0.0f);
            float4 hbv = make_float4(0.f, 0.f, 0.f, 0.f);
            const float4* h4 = (const float4*)(hist + (size_t)idx * NH * NU);
            while (mask) {
                int h = __ffs(mask) - 1;
                mask &= mask - 1;
                float wh = __shfl_sync(0xffffffffu, wv, h);
                float4 r4 = __ldg(h4 + h * 32 + lane);
                hbv.x = fmaf(wh, r4.x, hbv.x); hbv.y = fmaf(wh, r4.y, hbv.y);
                hbv.z = fmaf(wh, r4.z, hbv.z); hbv.w = fmaf(wh, r4.w, hbv.w);
            }
            ((float4*)(sX + r * NU))[lane] = hbv;
        }
    }
    __syncthreads();

    float4 a1[4];
#pragma unroll
    for (int i = 0; i < 4; ++i) a1[i] = make_float4(0.f, 0.f, 0.f, 0.f);
#pragma unroll 4
    for (int v = 0; v < NU; ++v) {
        float4 b = sW4[v * 16 + tx];
#pragma unroll
        for (int i = 0; i < 4; ++i) {
            float a = sX[(ty * 4 + i) * NU + v];
            a1[i].x = fmaf(a, b.x, a1[i].x);
            a1[i].y = fmaf(a, b.y, a1[i].y);
            a1[i].z = fmaf(a, b.z, a1[i].z);
            a1[i].w = fmaf(a, b.w, a1[i].w);
        }
    }
    __syncthreads();

    {
        const float4* w4 = (const float4*)(qw + (size_t)t * NU * NU);
#pragma unroll
        for (int i = threadIdx.x; i < 2048; i += 256)
            sW4[i] = w4[(i >> 4) * 32 + half * 16 + (i & 15)];
        float4* sX4 = (float4*)sX;
#pragma unroll
        for (int i = threadIdx.x; i < 2048; i += 256) {
            int r = i >> 5, c = i & 31;
            int idx = eidx[t * PT + n0 + r];
            sX4[i] = __ldg((const float4*)(state + (size_t)idx * NU) + c);
        }
    }
    __syncthreads();

    float4 a2[4];
#pragma unroll
    for (int i = 0; i < 4; ++i) a2[i] = make_float4(0.f, 0.f, 0.f, 0.f);
#pragma unroll 4
    for (int v = 0; v < NU; ++v) {
        float4 b = sW4[v * 16 + tx];
#pragma unroll
        for (int i = 0; i < 4; ++i) {
            float a = sX[(ty * 4 + i) * NU + v];
            a2[i].x = fmaf(a, b.x, a2[i].x);
            a2[i].y = fmaf(a, b.y, a2[i].y);
            a2[i].z = fmaf(a, b.z, a2[i].z);
            a2[i].w = fmaf(a, b.w, a2[i].w);
        }
    }

#pragma unroll
    for (int i = 0; i < 4; ++i) {
        size_t row = (size_t)t * PT + n0 + ty * 4 + i;
        float4 r;
        r.x = fmaxf(a1[i].x, 0.f) + a2[i].x;
        r.y = fmaxf(a1[i].y, 0.f) + a2[i].y;
        r.z = fmaxf(a1[i].z, 0.f) + a2[i].z;
        r.w = fmaxf(a1[i].w, 0.f) + a2[i].w;
        ((float4*)(out + row * NU))[half * 16 + tx] = r;
    }
}

// ---------------- launch: pure k1b stream + side-stream stats + fused epilogue ----------------
extern "C" void kernel_launch(void* const* d_in, const int* in_sizes, int n_in,
                              void* d_out, int out_size) {
    const float* state = (const float*)d_in[0];
    const float* hist  = (const float*)d_in[1];
    const int*   eidx  = (const int*)d_in[2];
    const float* qw    = (const float*)d_in[3];
    const float* kw    = (const float*)d_in[4];
    const float* vw    = (const float*)d_in[5];
    const float* fw    = (const float*)d_in[6];
    float* out = (float*)d_out;

    const int GSMEM = 64 * 1024;

    static bool init_done = false;
    static cudaStream_t s1, s2, s3;
    static cudaEvent_t eP, gE[NT], rE[NT], hE[NT], e1, e3, fE;
    static float* p_QKX;
    if (!init_done) {
        cudaFuncSetAttribute(kgemmH, cudaFuncAttributeMaxDynamicSharedMemorySize, GSMEM);
        cudaFuncSetAttribute(kout3, cudaFuncAttributeMaxDynamicSharedMemorySize, GSMEM);
        int lo, hi;
        cudaDeviceGetStreamPriorityRange(&lo, &hi);
        cudaStreamCreateWithPriority(&s1, cudaStreamNonBlocking, hi);           // k1b stream
        cudaStreamCreateWithPriority(&s2, cudaStreamNonBlocking, lo);           // epilogues
        cudaStreamCreateWithPriority(&s3, cudaStreamNonBlocking, (lo + hi) / 2); // stats
        cudaEventCreateWithFlags(&eP, cudaEventDisableTiming);
        for (int t = 0; t < NT; ++t) {
            cudaEventCreateWithFlags(&gE[t], cudaEventDisableTiming);
            cudaEventCreateWithFlags(&rE[t], cudaEventDisableTiming);
            cudaEventCreateWithFlags(&hE[t], cudaEventDisableTiming);
        }
        cudaEventCreateWithFlags(&e1, cudaEventDisableTiming);
        cudaEventCreateWithFlags(&e3, cudaEventDisableTiming);
        cudaEventCreateWithFlags(&fE, cudaEventDisableTiming);
        cudaGetSymbolAddress((void**)&p_QKX, g_QKX);
        init_done = true;
    }

    // ---- s0: prep + per-type QKX GEMMs ----
    ktrans<<<dim3(4, 4, NT), dim3(32, 8)>>>(kw);
    kqk<<<dim3(NU, NT), NU>>>(qw);
    cudaEventRecord(eP, 0);
    for (int t = 0; t < NT; ++t) {
        kgemmH<<<dim3(PT / 64, 2), 256, GSMEM>>>(state, eidx, t, p_QKX);
        cudaEventRecord(gE[t], 0);
    }

    // ---- s1 (high prio): pure back-to-back k1b stream ----
    for (int t = 0; t < NT; ++t) {
        cudaStreamWaitEvent(s1, gE[t], 0);
        k1b<<<PT / 4, 128, 0, s1>>>(hist, eidx, t);
        cudaEventRecord(rE[t], s1);
    }
    cudaEventRecord(e1, s1);

    // ---- s3 (mid prio): softmax stats, overlapped with next type's k1b ----
    for (int t = 0; t < NT; ++t) {
        cudaStreamWaitEvent(s3, rE[t], 0);
        k2t<<<NH, 256, 0, s3>>>(t);
        cudaEventRecord(hE[t], s3);
    }
    cudaEventRecord(e3, s3);

    // ---- s2 (low prio): kvf hidden; fully-fused epilogue per type ----
    cudaStreamWaitEvent(s2, eP, 0);
    kvf<<<dim3(NU, NT), NU, 0, s2>>>(vw, fw);
    for (int t = 0; t < NT; ++t) {
        cudaStreamWaitEvent(s2, hE[t], 0);
        kout3<<<dim3(PT / 64, 2), 256, GSMEM, s2>>>(state, hist, eidx, qw, out, t);
    }
    cudaEventRecord(fE, s2);

    // ---- join ----
    cudaStreamWaitEvent(0, e1, 0);
    cudaStreamWaitEvent(0, e3, 0);
    cudaStreamWaitEvent(0, fE, 0);
}

// round 17
// speedup vs baseline: 1.2378x; 1.0235x over previous
#include <cuda_runtime.h>
#include <math.h>

#define NT 4
#define PT 8192
#define NH 32
#define NU 128

// ---------------- scratch (device globals; no allocations) ----------------
__device__ float g_KT[NT * NU * NU];
__device__ float g_QK[NT * NU * NU];           // q_w @ k_w^T
__device__ float g_VF[NT * NU * NU];           // v_w @ fc_w
__device__ float g_QKX[(size_t)NT * PT * NU];  // x @ QK
__device__ float g_RAW[(size_t)NT * PT * NH];
__device__ float g_M[NT * NH];
__device__ float g_S[NT * NH];

// ---------------- prep ----------------
__global__ void __launch_bounds__(256) ktrans(const float* __restrict__ kw) {
    __shared__ float tile[32][33];
    int t = blockIdx.z;
    int bx = blockIdx.x * 32, by = blockIdx.y * 32;
    const float* src = kw + (size_t)t * NU * NU;
    float* dst = g_KT + (size_t)t * NU * NU;
    int tx = threadIdx.x, ty = threadIdx.y;
#pragma unroll
    for (int i = 0; i < 32; i += 8)
        tile[ty + i][tx] = src[(by + ty + i) * NU + bx + tx];
    __syncthreads();
#pragma unroll
    for (int i = 0; i < 32; i += 8)
        dst[(bx + ty + i) * NU + by + tx] = tile[tx][ty + i];
}

__global__ void __launch_bounds__(128) kqk(const float* __restrict__ qw) {
    int t = blockIdx.y, e = blockIdx.x, u = threadIdx.x;
    const float* q = qw + ((size_t)t * NU + e) * NU;
    const float* kt = g_KT + (size_t)t * NU * NU;
    float acc = 0.f;
#pragma unroll 8
    for (int v = 0; v < NU; ++v)
        acc = fmaf(q[v], kt[v * NU + u], acc);
    g_QK[((size_t)t * NU + e) * NU + u] = acc;
}

__global__ void __launch_bounds__(128) kvf(const float* __restrict__ vw,
                                           const float* __restrict__ fw) {
    int t = blockIdx.y, w = blockIdx.x, j = threadIdx.x;
    const float* vr = vw + ((size_t)t * NU + w) * NU;
    const float* f = fw + (size_t)t * NU * NU;
    float acc = 0.f;
#pragma unroll 8
    for (int u = 0; u < NU; ++u)
        acc = fmaf(vr[u], f[u * NU + j], acc);
    g_VF[((size_t)t * NU + w) * NU + j] = acc;
}

// ---- shared GEMM micro-kernel: acc[4 rows][float4 col] += sX rows @ sW half ----
// a-operand loaded as LDS.128 per row per v-block of 4.
__device__ __forceinline__ void gemm_tile(const float* sX, const float4* sW4,
                                          int tx, int ty, float4 acc[4]) {
#pragma unroll 4
    for (int v4 = 0; v4 < 32; ++v4) {
        float4 b0 = sW4[(4 * v4 + 0) * 16 + tx];
        float4 b1 = sW4[(4 * v4 + 1) * 16 + tx];
        float4 b2 = sW4[(4 * v4 + 2) * 16 + tx];
        float4 b3 = sW4[(4 * v4 + 3) * 16 + tx];
#pragma unroll
        for (int i = 0; i < 4; ++i) {
            float4 a = *(const float4*)&sX[(ty * 4 + i) * NU + 4 * v4];
            acc[i].x = fmaf(a.x, b0.x, acc[i].x); acc[i].y = fmaf(a.x, b0.y, acc[i].y);
            acc[i].z = fmaf(a.x, b0.z, acc[i].z); acc[i].w = fmaf(a.x, b0.w, acc[i].w);
            acc[i].x = fmaf(a.y, b1.x, acc[i].x); acc[i].y = fmaf(a.y, b1.y, acc[i].y);
            acc[i].z = fmaf(a.y, b1.z, acc[i].z); acc[i].w = fmaf(a.y, b1.w, acc[i].w);
            acc[i].x = fmaf(a.z, b2.x, acc[i].x); acc[i].y = fmaf(a.z, b2.y, acc[i].y);
            acc[i].z = fmaf(a.z, b2.z, acc[i].z); acc[i].w = fmaf(a.z, b2.w, acc[i].w);
            acc[i].x = fmaf(a.w, b3.x, acc[i].x); acc[i].y = fmaf(a.w, b3.y, acc[i].y);
            acc[i].z = fmaf(a.w, b3.z, acc[i].z); acc[i].w = fmaf(a.w, b3.w, acc[i].w);
        }
    }
}

// ============ split-N gathered GEMM: QKX[t][n][64*half..] = X[eidx] @ QK[:, half] ============
__global__ void __launch_bounds__(256) kgemmH(const float* __restrict__ state,
                                              const int* __restrict__ eidx,
                                              int t, float* __restrict__ dst) {
    extern __shared__ float smem[];
    float* sX = smem;                        // [64][128] = 32KB
    float4* sW4 = (float4*)(smem + 64 * NU); // [128][16] float4 = 32KB
    int n0 = blockIdx.x * 64;
    int half = blockIdx.y;

    const float4* w4 = (const float4*)(g_QK + (size_t)t * NU * NU);
#pragma unroll
    for (int i = threadIdx.x; i < 2048; i += 256)
        sW4[i] = w4[(i >> 4) * 32 + half * 16 + (i & 15)];

    float4* sX4 = (float4*)sX;
#pragma unroll
    for (int i = threadIdx.x; i < 2048; i += 256) {
        int r = i >> 5, c = i & 31;
        int idx = eidx[t * PT + n0 + r];
        sX4[i] = __ldg((const float4*)(state + (size_t)idx * NU) + c);
    }
    __syncthreads();

    int tx = threadIdx.x & 15;
    int ty = threadIdx.x >> 4;
    float4 acc[4];
#pragma unroll
    for (int i = 0; i < 4; ++i) acc[i] = make_float4(0.f, 0.f, 0.f, 0.f);
    gemm_tile(sX, sW4, tx, ty, acc);
#pragma unroll
    for (int i = 0; i < 4; ++i)
        ((float4*)(dst + ((size_t)t * PT + n0 + ty * 4 + i) * NU))[half * 16 + tx] = acc[i];
}

// ============ k1b(t): raw = hist . qkx — quarter-warp rows, evict-first stream ============
__global__ void __launch_bounds__(128) k1b(const float* __restrict__ hist,
                                           const int* __restrict__ eidx, int t) {
    int lane = threadIdx.x & 31;
    int warp = threadIdx.x >> 5;
    int n = blockIdx.x * 4 + warp;
    int idx = eidx[t * PT + n];
    int g = lane >> 3;
    int c = lane & 7;

    const float4* qkrow = (const float4*)(g_QKX + ((size_t)t * PT + n) * NU);
    float4 qk[4];
#pragma unroll
    for (int j = 0; j < 4; ++j) qk[j] = __ldg(qkrow + j * 8 + c);

    const float* hb = hist + (size_t)idx * NH * NU;
    float* rawdst = g_RAW + ((size_t)t * PT + n) * NH;
#pragma unroll
    for (int i = 0; i < 8; ++i) {
        const float4* rowp = (const float4*)(hb + (4 * i + g) * NU);
        float4 v0 = __ldcs(rowp + 0 * 8 + c);
        float4 v1 = __ldcs(rowp + 1 * 8 + c);
        float4 v2 = __ldcs(rowp + 2 * 8 + c);
        float4 v3 = __ldcs(rowp + 3 * 8 + c);
        float p = 0.f;
        p = fmaf(v0.x, qk[0].x, p); p = fmaf(v0.y, qk[0].y, p);
        p = fmaf(v0.z, qk[0].z, p); p = fmaf(v0.w, qk[0].w, p);
        p = fmaf(v1.x, qk[1].x, p); p = fmaf(v1.y, qk[1].y, p);
        p = fmaf(v1.z, qk[1].z, p); p = fmaf(v1.w, qk[1].w, p);
        p = fmaf(v2.x, qk[2].x, p); p = fmaf(v2.y, qk[2].y, p);
        p = fmaf(v2.z, qk[2].z, p); p = fmaf(v2.w, qk[2].w, p);
        p = fmaf(v3.x, qk[3].x, p); p = fmaf(v3.y, qk[3].y, p);
        p = fmaf(v3.w, qk[3].w, p); p = fmaf(v3.z, qk[3].z, p);
        p += __shfl_xor_sync(0xffffffffu, p, 4);
        p += __shfl_xor_sync(0xffffffffu, p, 2);
        p += __shfl_xor_sync(0xffffffffu, p, 1);
        if (c == 0) rawdst[4 * i + g] = p;
    }
}

// ---------------- k2t(t): softmax stats for one type ----------------
__global__ void __launch_bounds__(256) k2t(int t) {
    int h = blockIdx.x;
    const float* base = g_RAW + (size_t)t * PT * NH + h;
    __shared__ float rm[256], rs[256];
    int tid = threadIdx.x;

    float m = -3.402823466e+38f, s = 0.f;
    for (int n = tid; n < PT; n += 256) {
        float x = base[(size_t)n * NH];
        if (x > m) { s = s * expf(m - x) + 1.f; m = x; }
        else s += expf(x - m);
    }
    rm[tid] = m; rs[tid] = s;
    __syncthreads();
#pragma unroll
    for (int st = 128; st; st >>= 1) {
        if (tid < st) {
            float m2 = rm[tid + st], s2 = rs[tid + st];
            float M = fmaxf(rm[tid], m2);
            rs[tid] = rs[tid] * expf(rm[tid] - M) + s2 * expf(m2 - M);
            rm[tid] = M;
        }
        __syncthreads();
    }
    if (tid == 0) { g_M[t * NH + h] = rm[0]; g_S[t * NH + h] = rs[0]; }
}

// ============ kout3(t): sparse-hbar + relu(hbar @ VF) + X @ qw ============
// Sparse-hbar is bit-exact: fp32 softmax weights underflow to exactly 0.0 away from the
// per-(t,h) argmax; the fp32 reference underflows identically, and fmaf(0, x, a) == a.
__global__ void __launch_bounds__(256) kout3(const float* __restrict__ state,
                                             const float* __restrict__ hist,
                                             const int* __restrict__ eidx,
                                             const float* __restrict__ qw,
                                             float* __restrict__ out, int t) {
    extern __shared__ float smem[];
    float* sX = smem;                        // [64][128]
    float4* sW4 = (float4*)(smem + 64 * NU); // [128][16] float4
    int n0 = blockIdx.x * 64;
    int half = blockIdx.y;
    int lane = threadIdx.x & 31;
    int warp = threadIdx.x >> 5;
    int tx = threadIdx.x & 15;
    int ty = threadIdx.x >> 4;

    {
        const float4* w4 = (const float4*)(g_VF + (size_t)t * NU * NU);
#pragma unroll
        for (int i = threadIdx.x; i < 2048; i += 256)
            sW4[i] = w4[(i >> 4) * 32 + half * 16 + (i & 15)];
    }

    {
        float Mv = g_M[t * NH + lane];
        float Sv = g_S[t * NH + lane];
#pragma unroll
        for (int j = 0; j < 8; ++j) {
            int r = warp * 8 + j;
            int n = n0 + r;
            int idx = eidx[t * PT + n];
            float raw = g_RAW[((size_t)t * PT + n) * NH + lane];
            float wv = expf(raw - Mv) / Sv;
            unsigned mask = __ballot_sync(0xffffffffu, wv != 0.0f);
            float4 hbv = make_float4(0.f, 0.f, 0.f, 0.f);
            const float4* h4 = (const float4*)(hist + (size_t)idx * NH * NU);
            while (mask) {
                int h = __ffs(mask) - 1;
                mask &= mask - 1;
                float wh = __shfl_sync(0xffffffffu, wv, h);
                float4 r4 = __ldg(h4 + h * 32 + lane);
                hbv.x = fmaf(wh, r4.x, hbv.x); hbv.y = fmaf(wh, r4.y, hbv.y);
                hbv.z = fmaf(wh, r4.z, hbv.z); hbv.w = fmaf(wh, r4.w, hbv.w);
            }
            ((float4*)(sX + r * NU))[lane] = hbv;
        }
    }
    __syncthreads();

    float4 a1[4];
#pragma unroll
    for (int i = 0; i < 4; ++i) a1[i] = make_float4(0.f, 0.f, 0.f, 0.f);
    gemm_tile(sX, sW4, tx, ty, a1);
    __syncthreads();

    {
        const float4* w4 = (const float4*)(qw + (size_t)t * NU * NU);
#pragma unroll
        for (int i = threadIdx.x; i < 2048; i += 256)
            sW4[i] = w4[(i >> 4) * 32 + half * 16 + (i & 15)];
        float4* sX4 = (float4*)sX;
#pragma unroll
        for (int i = threadIdx.x; i < 2048; i += 256) {
            int r = i >> 5, c = i & 31;
            int idx = eidx[t * PT + n0 + r];
            sX4[i] = __ldg((const float4*)(state + (size_t)idx * NU) + c);
        }
    }
    __syncthreads();

    float4 a2[4];
#pragma unroll
    for (int i = 0; i < 4; ++i) a2[i] = make_float4(0.f, 0.f, 0.f, 0.f);
    gemm_tile(sX, sW4, tx, ty, a2);

#pragma unroll
    for (int i = 0; i < 4; ++i) {
        size_t row = (size_t)t * PT + n0 + ty * 4 + i;
        float4 r;
        r.x = fmaxf(a1[i].x, 0.f) + a2[i].x;
        r.y = fmaxf(a1[i].y, 0.f) + a2[i].y;
        r.z = fmaxf(a1[i].z, 0.f) + a2[i].z;
        r.w = fmaxf(a1[i].w, 0.f) + a2[i].w;
        ((float4*)(out + row * NU))[half * 16 + tx] = r;
    }
}

// ---------------- launch: pure k1b stream + side-stream stats + fused epilogue ----------------
extern "C" void kernel_launch(void* const* d_in, const int* in_sizes, int n_in,
                              void* d_out, int out_size) {
    const float* state = (const float*)d_in[0];
    const float* hist  = (const float*)d_in[1];
    const int*   eidx  = (const int*)d_in[2];
    const float* qw    = (const float*)d_in[3];
    const float* kw    = (const float*)d_in[4];
    const float* vw    = (const float*)d_in[5];
    const float* fw    = (const float*)d_in[6];
    float* out = (float*)d_out;

    const int GSMEM = 64 * 1024;

    static bool init_done = false;
    static cudaStream_t s1, s2, s3;
    static cudaEvent_t eP, gE[NT], rE[NT], hE[NT], e1, e3, fE;
    static float* p_QKX;
    if (!init_done) {
        cudaFuncSetAttribute(kgemmH, cudaFuncAttributeMaxDynamicSharedMemorySize, GSMEM);
        cudaFuncSetAttribute(kout3, cudaFuncAttributeMaxDynamicSharedMemorySize, GSMEM);
        int lo, hi;
        cudaDeviceGetStreamPriorityRange(&lo, &hi);
        cudaStreamCreateWithPriority(&s1, cudaStreamNonBlocking, hi);
        cudaStreamCreateWithPriority(&s2, cudaStreamNonBlocking, lo);
        cudaStreamCreateWithPriority(&s3, cudaStreamNonBlocking, (lo + hi) / 2);
        cudaEventCreateWithFlags(&eP, cudaEventDisableTiming);
        for (int t = 0; t < NT; ++t) {
            cudaEventCreateWithFlags(&gE[t], cudaEventDisableTiming);
            cudaEventCreateWithFlags(&rE[t], cudaEventDisableTiming);
            cudaEventCreateWithFlags(&hE[t], cudaEventDisableTiming);
        }
        cudaEventCreateWithFlags(&e1, cudaEventDisableTiming);
        cudaEventCreateWithFlags(&e3, cudaEventDisableTiming);
        cudaEventCreateWithFlags(&fE, cudaEventDisableTiming);
        cudaGetSymbolAddress((void**)&p_QKX, g_QKX);
        init_done = true;
    }

    // ---- s0: prep + per-type QKX GEMMs ----
    ktrans<<<dim3(4, 4, NT), dim3(32, 8)>>>(kw);
    kqk<<<dim3(NU, NT), NU>>>(qw);
    cudaEventRecord(eP, 0);
    for (int t = 0; t < NT; ++t) {
        kgemmH<<<dim3(PT / 64, 2), 256, GSMEM>>>(state, eidx, t, p_QKX);
        cudaEventRecord(gE[t], 0);
    }

    // ---- s1 (high prio): pure back-to-back k1b stream ----
    for (int t = 0; t < NT; ++t) {
        cudaStreamWaitEvent(s1, gE[t], 0);
        k1b<<<PT / 4, 128, 0, s1>>>(hist, eidx, t);
        cudaEventRecord(rE[t], s1);
    }
    cudaEventRecord(e1, s1);

    // ---- s3 (mid prio): softmax stats, overlapped with next type's k1b ----
    for (int t = 0; t < NT; ++t) {
        cudaStreamWaitEvent(s3, rE[t], 0);
        k2t<<<NH, 256, 0, s3>>>(t);
        cudaEventRecord(hE[t], s3);
    }
    cudaEventRecord(e3, s3);

    // ---- s2 (low prio): kvf hidden; fully-fused epilogue per type ----
    cudaStreamWaitEvent(s2, eP, 0);
    kvf<<<dim3(NU, NT), NU, 0, s2>>>(vw, fw);
    for (int t = 0; t < NT; ++t) {
        cudaStreamWaitEvent(s2, hE[t], 0);
        kout3<<<dim3(PT / 64, 2), 256, GSMEM, s2>>>(state, hist, eidx, qw, out, t);
    }
    cudaEventRecord(fE, s2);

    // ---- join ----
    cudaStreamWaitEvent(0, e1, 0);
    cudaStreamWaitEvent(0, e3, 0);
    cudaStreamWaitEvent(0, fE, 0);
}